// round 14
// baseline (speedup 1.0000x reference)
#include <cuda_runtime.h>
#include <cstdint>

// Input:  image [256, 384, 384] float32   (i, j, c')
// Output: out   [1, 384, 320, 512] float32 (j, a, c)
//
// Separable bilinear, rational scales => fixed weights:
//   c: 384 -> 512 (x4/3): outputs 4k..4k+3 <- inputs 3k-1..3k+3,
//      weights {0.875, 0.625, 0.375, 0.125}
//   a: 256 -> 320 (x5/4): outputs 5m..5m+4 <- rows 4m-1..4m+4,
//      weights {0.9, 0.7, 0.5, 0.3, 0.1}
// Boundary clamps degenerate (x[i]==x[i+1]) so fixed weights hold everywhere.
//
// R14 = R9 (champion, 63.4us) with a sharpened L2 policy split:
//   interior single-use rows      -> __ldcs           (evict-first)
//   boundary rows shared across adjacent m2 blocks
//                                 -> ld.global.nc.L2::evict_last (pinned until
//                                    the second reader arrives)

#define D0 256
#define D1 384
#define D2 384
#define S0 320
#define S1 384
#define S2 512

#define ROWS_SM 10          // input rows staged per block
#define THREADS 256

__global__ __launch_bounds__(THREADS)
void resize3d_kernel(const float* __restrict__ in, float* __restrict__ out) {
    __shared__ float sm[ROWS_SM][D2];

    const int tid = threadIdx.x;
    const int m2 = blockIdx.x;      // 0..31: pair of a-groups
    const int j  = blockIdx.y;      // 0..383

    // ---- Phase 1: coalesced float4 staging of 10 input rows ----
    // slot t <- input row clamp(8*m2 - 1 + t, 0, 255)
    {
        uint64_t pol;
        asm("createpolicy.fractional.L2::evict_last.b64 %0, 1.0;" : "=l"(pol));

        const int base_row = 8 * m2 - 1;
        #pragma unroll
        for (int idx = tid; idx < ROWS_SM * (D2 / 4); idx += THREADS) {
            int t = idx / (D2 / 4);
            int q = idx % (D2 / 4);
            int g = min(max(base_row + t, 0), D0 - 1);
            const float4* rp = (const float4*)(in + ((size_t)g * D1 + j) * D2) + q;
            float4 v;
            if (t <= 1 || t >= 8) {
                // shared with the adjacent m2 block: pin in L2 until re-read
                asm volatile(
                    "ld.global.nc.L2::cache_hint.v4.f32 {%0,%1,%2,%3}, [%4], %5;"
                    : "=f"(v.x), "=f"(v.y), "=f"(v.z), "=f"(v.w)
                    : "l"(rp), "l"(pol));
            } else {
                // single-use interior row: stream, don't pollute L2
                v = __ldcs(rp);
            }
            ((float4*)sm[t])[q] = v;
        }
    }
    __syncthreads();

    // ---- Phase 2: interpolate ----
    const int k = tid & 127;        // c-group 0..127 -> output cols 4k..4k+3
    const int y = tid >> 7;         // 0..1: a-group of the pair
    const int m = 2 * m2 + y;

    const int col0 = max(3 * k - 1, 0);
    const int col1 = 3 * k;
    const int col4 = min(3 * k + 3, D2 - 1);
    const int t0 = 4 * y;           // smem slots t0..t0+5 = rows 4m-1..4m+4

    float l[6][4];
    #pragma unroll
    for (int t = 0; t < 6; ++t) {
        const float* r = sm[t0 + t];
        float x0 = r[col0];
        float x1 = r[col1];
        float x2 = r[col1 + 1];
        float x3 = r[col1 + 2];
        float x4 = r[col4];
        l[t][0] = x0 + 0.875f * (x1 - x0);
        l[t][1] = x1 + 0.625f * (x2 - x1);
        l[t][2] = x2 + 0.375f * (x3 - x2);
        l[t][3] = x3 + 0.125f * (x4 - x3);
    }

    float4* op = (float4*)(out + ((size_t)j * S0 + 5 * m) * S2 + 4 * k);
    const float wa[5] = {0.9f, 0.7f, 0.5f, 0.3f, 0.1f};

    #pragma unroll
    for (int s = 0; s < 5; ++s) {
        float w = wa[s];
        float4 o;
        o.x = l[s][0] + w * (l[s + 1][0] - l[s][0]);
        o.y = l[s][1] + w * (l[s + 1][1] - l[s][1]);
        o.z = l[s][2] + w * (l[s + 1][2] - l[s][2]);
        o.w = l[s][3] + w * (l[s + 1][3] - l[s][3]);
        __stcs(op, o);
        op += S2 / 4;
    }
}

extern "C" void kernel_launch(void* const* d_in, const int* in_sizes, int n_in,
                              void* d_out, int out_size) {
    (void)in_sizes; (void)n_in; (void)out_size;
    const float* in = (const float*)d_in[0];
    float* out = (float*)d_out;

    dim3 grid(S0 / 5 / 2, S1, 1);   // (a-group pairs fastest -> L2 row sharing, j)
    dim3 block(THREADS, 1, 1);
    resize3d_kernel<<<grid, block>>>(in, out);
}

// round 15
// speedup vs baseline: 1.0010x; 1.0010x over previous
#include <cuda_runtime.h>

// Input:  image [256, 384, 384] float32   (i, j, c')
// Output: out   [1, 384, 320, 512] float32 (j, a, c)
//
// Separable bilinear, rational scales => fixed weights:
//   c: 384 -> 512 (x4/3): outputs 4k..4k+3 <- inputs 3k-1..3k+3,
//      weights {0.875, 0.625, 0.375, 0.125}
//   a: 256 -> 320 (x5/4): outputs 5m..5m+4 <- rows 4m-1..4m+4,
//      weights {0.9, 0.7, 0.5, 0.3, 0.1}
// Boundary clamps degenerate (x[i]==x[i+1]) so fixed weights hold everywhere.
//
// FINAL CHAMPION (R9, 63.4us, ~6.8 TB/s effective ~ 85% of HBM spec):
//   Phase 1: 10 input rows staged to smem via coalesced float4 loads;
//            single-use interior rows use __ldcs (L2 evict-first),
//            block-shared boundary rows use __ldg (default caching).
//   Phase 2: 256 threads = 128 c-groups x 2 a-groups; stride-3 smem taps
//            (gcd(3,32)=1 -> conflict-free), c-lerp + a-lerp,
//            5 float4 streaming stores (__stcs) per thread.

#define D0 256
#define D1 384
#define D2 384
#define S0 320
#define S1 384
#define S2 512

#define ROWS_SM 10          // input rows staged per block
#define THREADS 256

__global__ __launch_bounds__(THREADS)
void resize3d_kernel(const float* __restrict__ in, float* __restrict__ out) {
    __shared__ float sm[ROWS_SM][D2];

    const int tid = threadIdx.x;
    const int m2 = blockIdx.x;      // 0..31: pair of a-groups
    const int j  = blockIdx.y;      // 0..383

    // ---- Phase 1: coalesced float4 staging of 10 input rows ----
    // slot t <- input row clamp(8*m2 - 1 + t, 0, 255)
    {
        const int base_row = 8 * m2 - 1;
        #pragma unroll
        for (int idx = tid; idx < ROWS_SM * (D2 / 4); idx += THREADS) {
            int t = idx / (D2 / 4);
            int q = idx % (D2 / 4);
            int g = min(max(base_row + t, 0), D0 - 1);
            const float4* rp = (const float4*)(in + ((size_t)g * D1 + j) * D2);
            // slots 0,1 and 8,9 are shared with the adjacent m2 block ->
            // keep cacheable; interior rows are single-use -> streaming.
            float4 v = (t <= 1 || t >= 8) ? __ldg(rp + q) : __ldcs(rp + q);
            ((float4*)sm[t])[q] = v;
        }
    }
    __syncthreads();

    // ---- Phase 2: interpolate ----
    const int k = tid & 127;        // c-group 0..127 -> output cols 4k..4k+3
    const int y = tid >> 7;         // 0..1: a-group of the pair
    const int m = 2 * m2 + y;

    const int col0 = max(3 * k - 1, 0);
    const int col1 = 3 * k;
    const int col4 = min(3 * k + 3, D2 - 1);
    const int t0 = 4 * y;           // smem slots t0..t0+5 = rows 4m-1..4m+4

    float l[6][4];
    #pragma unroll
    for (int t = 0; t < 6; ++t) {
        const float* r = sm[t0 + t];
        float x0 = r[col0];
        float x1 = r[col1];
        float x2 = r[col1 + 1];
        float x3 = r[col1 + 2];
        float x4 = r[col4];
        l[t][0] = x0 + 0.875f * (x1 - x0);
        l[t][1] = x1 + 0.625f * (x2 - x1);
        l[t][2] = x2 + 0.375f * (x3 - x2);
        l[t][3] = x3 + 0.125f * (x4 - x3);
    }

    float4* op = (float4*)(out + ((size_t)j * S0 + 5 * m) * S2 + 4 * k);
    const float wa[5] = {0.9f, 0.7f, 0.5f, 0.3f, 0.1f};

    #pragma unroll
    for (int s = 0; s < 5; ++s) {
        float w = wa[s];
        float4 o;
        o.x = l[s][0] + w * (l[s + 1][0] - l[s][0]);
        o.y = l[s][1] + w * (l[s + 1][1] - l[s][1]);
        o.z = l[s][2] + w * (l[s + 1][2] - l[s][2]);
        o.w = l[s][3] + w * (l[s + 1][3] - l[s][3]);
        __stcs(op, o);
        op += S2 / 4;
    }
}

extern "C" void kernel_launch(void* const* d_in, const int* in_sizes, int n_in,
                              void* d_out, int out_size) {
    (void)in_sizes; (void)n_in; (void)out_size;
    const float* in = (const float*)d_in[0];
    float* out = (float*)d_out;

    dim3 grid(S0 / 5 / 2, S1, 1);   // (a-group pairs fastest -> L2 row sharing, j)
    dim3 block(THREADS, 1, 1);
    resize3d_kernel<<<grid, block>>>(in, out);
}

// round 16
// speedup vs baseline: 1.0269x; 1.0258x over previous
#include <cuda_runtime.h>

// Input:  image [256, 384, 384] float32   (i, j, c')
// Output: out   [1, 384, 320, 512] float32 (j, a, c)
//
// Separable bilinear, rational scales => fixed weights:
//   c: 384 -> 512 (x4/3): outputs 4k..4k+3 <- inputs 3k-1..3k+3,
//      weights {0.875, 0.625, 0.375, 0.125}
//   a: 256 -> 320 (x5/4): outputs 5m..5m+4 <- rows 4m-1..4m+4,
//      weights {0.9, 0.7, 0.5, 0.3, 0.1}
// Boundary clamps degenerate (x[i]==x[i+1]) so fixed weights hold everywhere.
//
// R16 = R9 kernel body, grid order swapped: j is now the fastest grid dim.
// A concurrent wave (~1184 blocks) covers m2 in {0..3} x all j -> input
// working set ~25 MB (fits L2), sequential DRAM read slabs per m2, and
// near-guaranteed L2 hits on the boundary rows shared across adjacent m2.

#define D0 256
#define D1 384
#define D2 384
#define S0 320
#define S1 384
#define S2 512

#define ROWS_SM 10          // input rows staged per block
#define THREADS 256

__global__ __launch_bounds__(THREADS)
void resize3d_kernel(const float* __restrict__ in, float* __restrict__ out) {
    __shared__ float sm[ROWS_SM][D2];

    const int tid = threadIdx.x;
    const int j  = blockIdx.x;      // 0..383 (fastest -> wave-local input slab)
    const int m2 = blockIdx.y;      // 0..31: pair of a-groups

    // ---- Phase 1: coalesced float4 staging of 10 input rows ----
    // slot t <- input row clamp(8*m2 - 1 + t, 0, 255)
    {
        const int base_row = 8 * m2 - 1;
        #pragma unroll
        for (int idx = tid; idx < ROWS_SM * (D2 / 4); idx += THREADS) {
            int t = idx / (D2 / 4);
            int q = idx % (D2 / 4);
            int g = min(max(base_row + t, 0), D0 - 1);
            const float4* rp = (const float4*)(in + ((size_t)g * D1 + j) * D2);
            // slots 0,1 and 8,9 are shared with the adjacent m2 wave ->
            // keep cacheable; interior rows are single-use -> streaming.
            float4 v = (t <= 1 || t >= 8) ? __ldg(rp + q) : __ldcs(rp + q);
            ((float4*)sm[t])[q] = v;
        }
    }
    __syncthreads();

    // ---- Phase 2: interpolate ----
    const int k = tid & 127;        // c-group 0..127 -> output cols 4k..4k+3
    const int y = tid >> 7;         // 0..1: a-group of the pair
    const int m = 2 * m2 + y;

    const int col0 = max(3 * k - 1, 0);
    const int col1 = 3 * k;
    const int col4 = min(3 * k + 3, D2 - 1);
    const int t0 = 4 * y;           // smem slots t0..t0+5 = rows 4m-1..4m+4

    float l[6][4];
    #pragma unroll
    for (int t = 0; t < 6; ++t) {
        const float* r = sm[t0 + t];
        float x0 = r[col0];
        float x1 = r[col1];
        float x2 = r[col1 + 1];
        float x3 = r[col1 + 2];
        float x4 = r[col4];
        l[t][0] = x0 + 0.875f * (x1 - x0);
        l[t][1] = x1 + 0.625f * (x2 - x1);
        l[t][2] = x2 + 0.375f * (x3 - x2);
        l[t][3] = x3 + 0.125f * (x4 - x3);
    }

    float4* op = (float4*)(out + ((size_t)j * S0 + 5 * m) * S2 + 4 * k);
    const float wa[5] = {0.9f, 0.7f, 0.5f, 0.3f, 0.1f};

    #pragma unroll
    for (int s = 0; s < 5; ++s) {
        float w = wa[s];
        float4 o;
        o.x = l[s][0] + w * (l[s + 1][0] - l[s][0]);
        o.y = l[s][1] + w * (l[s + 1][1] - l[s][1]);
        o.z = l[s][2] + w * (l[s + 1][2] - l[s][2]);
        o.w = l[s][3] + w * (l[s + 1][3] - l[s][3]);
        __stcs(op, o);
        op += S2 / 4;
    }
}

extern "C" void kernel_launch(void* const* d_in, const int* in_sizes, int n_in,
                              void* d_out, int out_size) {
    (void)in_sizes; (void)n_in; (void)out_size;
    const float* in = (const float*)d_in[0];
    float* out = (float*)d_out;

    dim3 grid(S1, S0 / 5 / 2, 1);   // (j fastest, a-group pairs)
    dim3 block(THREADS, 1, 1);
    resize3d_kernel<<<grid, block>>>(in, out);
}